// round 7
// baseline (speedup 1.0000x reference)
#include <cuda_runtime.h>
#include <cuda_bf16.h>
#include <cstdint>

// Constants: B=16, C=128, T=8, BR=16, S=8, SY=64, INPUT_SIZE=16384, C*T*BR=16384
// seg_on = (count>=16 of 64), branch_on = (count>=4 of 8)
// Output = layer2 branch_on at t==0 -> (16,128,16) float32

#define NB 512   // persistent blocks; 6 blocks/SM capacity * 148 SMs = 888 >= 512

__device__ __align__(16) uint16_t g_xbits[16384];
__device__ __align__(16) uint16_t g_act1[16384];
__device__ unsigned g_count = 0;
__device__ unsigned g_gen   = 0;

__device__ __forceinline__ uint32_t maj3(uint32_t a, uint32_t b, uint32_t c) {
    return (a & b) | (a & c) | (b & c);
}

#define SHFLX(v, m) __shfl_xor_sync(0xffffffffu, (v), (m))

// Software grid barrier (sense-reversal; g_count self-resets -> replay-safe).
__device__ __forceinline__ void grid_barrier() {
    __threadfence();
    __syncthreads();
    if (threadIdx.x == 0) {
        unsigned gen = *(volatile unsigned*)&g_gen;
        if (atomicAdd(&g_count, 1u) == NB - 1u) {
            atomicExch(&g_count, 0u);
            __threadfence();
            atomicAdd(&g_gen, 1u);
        } else {
            while (*(volatile unsigned*)&g_gen == gen) { __nanosleep(32); }
        }
    }
    __syncthreads();
    __threadfence();
}

// 8 lanes cooperate on one 64-synapse segment; returns on all 8 lanes the
// 16-bit batch mask of (segment count >= 16).
__device__ __forceinline__ uint32_t seg_ge16_warp(const int4* __restrict__ p,
                                                  const uint16_t* __restrict__ sx) {
    int4 a = p[0];
    int4 b = p[1];
    uint32_t m0 = sx[a.x + 1], m1 = sx[a.y + 1], m2 = sx[a.z + 1], m3 = sx[a.w + 1];
    uint32_t m4 = sx[b.x + 1], m5 = sx[b.y + 1], m6 = sx[b.z + 1], m7 = sx[b.w + 1];

    uint32_t s1 = m0 ^ m1 ^ m2, c1 = maj3(m0, m1, m2);
    uint32_t s2 = m3 ^ m4 ^ m5, c2 = maj3(m3, m4, m5);
    uint32_t s3 = s1 ^ s2 ^ m6, c3 = maj3(s1, s2, m6);
    uint32_t w1 = s3 ^ m7,      c4 = s3 & m7;
    uint32_t s4 = c1 ^ c2 ^ c3, c5 = maj3(c1, c2, c3);
    uint32_t w2 = s4 ^ c4,      c6 = s4 & c4;
    uint32_t w4 = c5 ^ c6,      w8 = c5 & c6;

    uint32_t r0 = SHFLX(w1, 1), r1 = SHFLX(w2, 1), r2 = SHFLX(w4, 1), r3 = SHFLX(w8, 1);
    uint32_t k  = w1 & r0;
    uint32_t t0 = w1 ^ r0;
    uint32_t t1 = w2 ^ r1 ^ k;  k = maj3(w2, r1, k);
    uint32_t t2 = w4 ^ r2 ^ k;  k = maj3(w4, r2, k);
    uint32_t t3 = w8 ^ r3 ^ k;
    uint32_t t4 = maj3(w8, r3, k);

    r0 = SHFLX(t0, 2); r1 = SHFLX(t1, 2); r2 = SHFLX(t2, 2); r3 = SHFLX(t3, 2);
    uint32_t r4 = SHFLX(t4, 2);
    k = t0 & r0;
    uint32_t u0 = t0 ^ r0;
    uint32_t u1 = t1 ^ r1 ^ k;  k = maj3(t1, r1, k);
    uint32_t u2 = t2 ^ r2 ^ k;  k = maj3(t2, r2, k);
    uint32_t u3 = t3 ^ r3 ^ k;  k = maj3(t3, r3, k);
    uint32_t u4 = t4 ^ r4 ^ k;
    uint32_t u5 = maj3(t4, r4, k);

    r0 = SHFLX(u0, 4); r1 = SHFLX(u1, 4); r2 = SHFLX(u2, 4); r3 = SHFLX(u3, 4);
    r4 = SHFLX(u4, 4); uint32_t r5 = SHFLX(u5, 4);
    k = u0 & r0;
    k = maj3(u1, r1, k);
    k = maj3(u2, r2, k);
    k = maj3(u3, r3, k);
    return u4 | r4 | k | u5 | r5;
}

__device__ __forceinline__ uint32_t branch_ge4(const uint32_t* s) {
    uint32_t o01 = s[0] ^ s[1], t01 = s[0] & s[1];
    uint32_t o23 = s[2] ^ s[3], t23 = s[2] & s[3];
    uint32_t o45 = s[4] ^ s[5], t45 = s[4] & s[5];
    uint32_t o67 = s[6] ^ s[7], t67 = s[6] & s[7];
    uint32_t ca  = o01 & o23;
    uint32_t o03 = o01 ^ o23;
    uint32_t t03 = t01 ^ t23 ^ ca;
    uint32_t f03 = maj3(t01, t23, ca);
    uint32_t cb  = o45 & o67;
    uint32_t o47 = o45 ^ o67;
    uint32_t t47 = t45 ^ t67 ^ cb;
    uint32_t f47 = maj3(t45, t67, cb);
    uint32_t c1 = o03 & o47;
    uint32_t c2 = maj3(t03, t47, c1);
    return f03 | f47 | c2;
}

__device__ __forceinline__ void fill_table(uint16_t* sx, const uint16_t* gtab) {
    if (threadIdx.x == 0) sx[0] = 0;
    const uint32_t* src = reinterpret_cast<const uint32_t*>(gtab);
    for (int i = threadIdx.x; i < 8192; i += 256) {
        uint32_t v = src[i];
        sx[1 + 2 * i] = (uint16_t)(v & 0xFFFFu);
        sx[2 + 2 * i] = (uint16_t)(v >> 16);
    }
    __syncthreads();
}

__global__ void __launch_bounds__(256) k_all(const float* __restrict__ x,
                                             const int* __restrict__ idx1,
                                             const int* __restrict__ idx2,
                                             float* __restrict__ out) {
    __shared__ uint16_t sx[16386];
    __shared__ uint32_t segbuf[8][32];

    int tid = threadIdx.x;
    int w = tid >> 5, lane = tid & 31;
    int pos = lane & 7, sg = lane >> 3;

    // ---- Phase A: pack x into 16-bit batch masks (blocks 0..63) ----
    if (blockIdx.x < 64) {
        int j = blockIdx.x * 256 + tid;
        uint32_t m = 0;
#pragma unroll
        for (int b = 0; b < 16; b++)
            m |= (x[b * 16384 + j] != 0.0f) ? (1u << b) : 0u;
        g_xbits[j] = (uint16_t)m;
    }
    grid_barrier();

    // ---- Phase B: layer 1, one 4-branch unit per warp (4096 warps) ----
    fill_table(sx, g_xbits);
    {
        int bb = (blockIdx.x * 8 + w) * 4;          // first branch of this warp's unit
#pragma unroll
        for (int kk = 0; kk < 8; kk++) {
            int branch = bb + (kk >> 1);
            int seg = ((kk & 1) << 2) + sg;
            const int4* p = reinterpret_cast<const int4*>(
                idx1 + branch * 512 + seg * 64 + pos * 8);
            uint32_t g = seg_ge16_warp(p, sx);
            if (pos == 0) segbuf[w][(kk >> 1) * 8 + seg] = g;
        }
        __syncwarp();
        if (lane < 4) {
            uint32_t ge4 = branch_ge4(&segbuf[w][lane * 8]);
            g_act1[bb + lane] = (uint16_t)ge4;
        }
    }
    grid_barrier();

    // ---- Phase C: layer 2 (t == 0 only), blocks 0..255, 1 branch per warp ----
    if (blockIdx.x < 256) {
        fill_table(sx, g_act1);
        int pr = blockIdx.x * 8 + w;                // branch id = c*16 + br
        int c = pr >> 4, br = pr & 15;
#pragma unroll
        for (int kk = 0; kk < 2; kk++) {
            int seg = (kk << 2) + sg;
            const int4* p = reinterpret_cast<const int4*>(
                idx2 + (c * 1024 + br * 8 + seg) * 64 + pos * 8);
            uint32_t g = seg_ge16_warp(p, sx);
            if (pos == 0) segbuf[w][seg] = g;
        }
        __syncwarp();
        if (lane == 0) {
            uint32_t ge4 = branch_ge4(&segbuf[w][0]);
#pragma unroll
            for (int b = 0; b < 16; b++)
                out[(b * 128 + c) * 16 + br] = ((ge4 >> b) & 1u) ? 1.0f : 0.0f;
        }
    }
}

extern "C" void kernel_launch(void* const* d_in, const int* in_sizes, int n_in,
                              void* d_out, int out_size) {
    const float* x = nullptr;
    const int* idxA = nullptr;
    const int* idxB = nullptr;
    for (int i = 0; i < n_in; i++) {
        if (in_sizes[i] == 262144 && !x) {
            x = (const float*)d_in[i];
        } else if (!idxA) {
            idxA = (const int*)d_in[i];
        } else if (!idxB) {
            idxB = (const int*)d_in[i];
        }
    }
    if (!x) { x = (const float*)d_in[0]; idxA = (const int*)d_in[1]; idxB = (const int*)d_in[2]; }

    float* out = (float*)d_out;   // (16, 128, 16) float32

    k_all<<<NB, 256>>>(x, idxA, idxB, out);
}

// round 8
// speedup vs baseline: 1.0986x; 1.0986x over previous
#include <cuda_runtime.h>
#include <cuda_bf16.h>
#include <cstdint>

// Constants: B=16, C=128, T=8, BR=16, S=8, SY=64, INPUT_SIZE=16384, C*T*BR=16384
// seg_on = (count>=16 of 64), branch_on = (count>=4 of 8)
// Output = layer2 branch_on at t==0 -> (16,128,16) float32

__device__ __align__(16) uint16_t g_xbits[16384];
__device__ __align__(16) uint16_t g_act1[16384];

__device__ __forceinline__ uint32_t maj3(uint32_t a, uint32_t b, uint32_t c) {
    return (a & b) | (a & c) | (b & c);
}

#define SHFLX(v, m) __shfl_xor_sync(0xffffffffu, (v), (m))

// 8 lanes cooperate on one 64-synapse segment (indices already in registers);
// returns on all 8 lanes the 16-bit batch mask of (segment count >= 16).
__device__ __forceinline__ uint32_t seg_ge16_regs(int4 a, int4 b,
                                                  const uint16_t* __restrict__ sx) {
    uint32_t m0 = sx[a.x + 1], m1 = sx[a.y + 1], m2 = sx[a.z + 1], m3 = sx[a.w + 1];
    uint32_t m4 = sx[b.x + 1], m5 = sx[b.y + 1], m6 = sx[b.z + 1], m7 = sx[b.w + 1];

    uint32_t s1 = m0 ^ m1 ^ m2, c1 = maj3(m0, m1, m2);
    uint32_t s2 = m3 ^ m4 ^ m5, c2 = maj3(m3, m4, m5);
    uint32_t s3 = s1 ^ s2 ^ m6, c3 = maj3(s1, s2, m6);
    uint32_t w1 = s3 ^ m7,      c4 = s3 & m7;
    uint32_t s4 = c1 ^ c2 ^ c3, c5 = maj3(c1, c2, c3);
    uint32_t w2 = s4 ^ c4,      c6 = s4 & c4;
    uint32_t w4 = c5 ^ c6,      w8 = c5 & c6;

    uint32_t r0 = SHFLX(w1, 1), r1 = SHFLX(w2, 1), r2 = SHFLX(w4, 1), r3 = SHFLX(w8, 1);
    uint32_t k  = w1 & r0;
    uint32_t t0 = w1 ^ r0;
    uint32_t t1 = w2 ^ r1 ^ k;  k = maj3(w2, r1, k);
    uint32_t t2 = w4 ^ r2 ^ k;  k = maj3(w4, r2, k);
    uint32_t t3 = w8 ^ r3 ^ k;
    uint32_t t4 = maj3(w8, r3, k);

    r0 = SHFLX(t0, 2); r1 = SHFLX(t1, 2); r2 = SHFLX(t2, 2); r3 = SHFLX(t3, 2);
    uint32_t r4 = SHFLX(t4, 2);
    k = t0 & r0;
    uint32_t u0 = t0 ^ r0;
    uint32_t u1 = t1 ^ r1 ^ k;  k = maj3(t1, r1, k);
    uint32_t u2 = t2 ^ r2 ^ k;  k = maj3(t2, r2, k);
    uint32_t u3 = t3 ^ r3 ^ k;  k = maj3(t3, r3, k);
    uint32_t u4 = t4 ^ r4 ^ k;
    uint32_t u5 = maj3(t4, r4, k);

    r0 = SHFLX(u0, 4); r1 = SHFLX(u1, 4); r2 = SHFLX(u2, 4); r3 = SHFLX(u3, 4);
    r4 = SHFLX(u4, 4); uint32_t r5 = SHFLX(u5, 4);
    k = u0 & r0;
    k = maj3(u1, r1, k);
    k = maj3(u2, r2, k);
    k = maj3(u3, r3, k);
    return u4 | r4 | k | u5 | r5;
}

__device__ __forceinline__ uint32_t branch_ge4(const uint32_t* s) {
    uint32_t o01 = s[0] ^ s[1], t01 = s[0] & s[1];
    uint32_t o23 = s[2] ^ s[3], t23 = s[2] & s[3];
    uint32_t o45 = s[4] ^ s[5], t45 = s[4] & s[5];
    uint32_t o67 = s[6] ^ s[7], t67 = s[6] & s[7];
    uint32_t ca  = o01 & o23;
    uint32_t o03 = o01 ^ o23;
    uint32_t t03 = t01 ^ t23 ^ ca;
    uint32_t f03 = maj3(t01, t23, ca);
    uint32_t cb  = o45 & o67;
    uint32_t o47 = o45 ^ o67;
    uint32_t t47 = t45 ^ t67 ^ cb;
    uint32_t f47 = maj3(t45, t67, cb);
    uint32_t c1 = o03 & o47;
    uint32_t c2 = maj3(t03, t47, c1);
    return f03 | f47 | c2;
}

__device__ __forceinline__ void fill_table(uint16_t* sx, const uint16_t* gtab) {
    if (threadIdx.x == 0) sx[0] = 0;
    const uint32_t* src = reinterpret_cast<const uint32_t*>(gtab);
    for (int i = threadIdx.x; i < 8192; i += 256) {
        uint32_t v = src[i];
        sx[1 + 2 * i] = (uint16_t)(v & 0xFFFFu);
        sx[2 + 2 * i] = (uint16_t)(v >> 16);
    }
    __syncthreads();
}

// Pack x (16 x 16384 floats of {0,1}) into per-position 16-bit batch masks.
__global__ void __launch_bounds__(256) k_pack(const float* __restrict__ x) {
    int j = blockIdx.x * 256 + threadIdx.x;
    float v[16];
#pragma unroll
    for (int b = 0; b < 16; b++) v[b] = x[b * 16384 + j];
    uint32_t m = 0;
#pragma unroll
    for (int b = 0; b < 16; b++)
        m |= (v[b] != 0.0f) ? (1u << b) : 0u;
    g_xbits[j] = (uint16_t)m;
}

// Layer 1: 512 blocks x 8 warps; warp covers 4 branches = 8 kk slices of
// (4 segments x 8 lanes). Address of slice kk = base + kk*256 ints (1KB).
// Depth-2 register prefetch to keep >=4 independent LDG.128 in flight.
__global__ void __launch_bounds__(256, 4) k_layer1(const int* __restrict__ idx) {
    __shared__ uint16_t sx[16386];
    __shared__ uint32_t segbuf[8][32];
    fill_table(sx, g_xbits);

    int w = threadIdx.x >> 5, lane = threadIdx.x & 31;
    int pos = lane & 7, sg = lane >> 3;
    int bb = (blockIdx.x * 8 + w) * 4;
    const int* base = idx + bb * 512 + sg * 64 + pos * 8;

    int4 pa[2], pb[2];
    pa[0] = *reinterpret_cast<const int4*>(base);
    pb[0] = *reinterpret_cast<const int4*>(base + 4);
    pa[1] = *reinterpret_cast<const int4*>(base + 256);
    pb[1] = *reinterpret_cast<const int4*>(base + 260);
#pragma unroll
    for (int kk = 0; kk < 8; kk++) {
        int4 A = pa[kk & 1], Bv = pb[kk & 1];
        if (kk + 2 < 8) {
            pa[kk & 1] = *reinterpret_cast<const int4*>(base + (kk + 2) * 256);
            pb[kk & 1] = *reinterpret_cast<const int4*>(base + (kk + 2) * 256 + 4);
        }
        uint32_t g = seg_ge16_regs(A, Bv, sx);
        if (pos == 0) segbuf[w][kk * 4 + sg] = g;
    }
    __syncwarp();
    if (lane < 4) {
        uint32_t ge4 = branch_ge4(&segbuf[w][lane * 8]);
        g_act1[bb + lane] = (uint16_t)ge4;
    }
}

// Layer 2 (t==0 only): 256 blocks x 8 warps; warp covers 1 branch
// (2 kk slices). All 4 int4 loads issued up front.
__global__ void __launch_bounds__(256, 4) k_layer2(const int* __restrict__ idx,
                                                   float* __restrict__ out) {
    __shared__ uint16_t sx[16386];
    __shared__ uint32_t segbuf[8][8];
    fill_table(sx, g_act1);

    int w = threadIdx.x >> 5, lane = threadIdx.x & 31;
    int pos = lane & 7, sg = lane >> 3;
    int pr = blockIdx.x * 8 + w;                  // branch id = c*16 + br
    int c = pr >> 4, br = pr & 15;
    // idx2 flat offset of (c, t=0, br, seg, pos*8), seg = kk*4 + sg
    const int* base = idx + (c * 1024 + br * 8 + sg) * 64 + pos * 8;

    int4 a0 = *reinterpret_cast<const int4*>(base);
    int4 b0 = *reinterpret_cast<const int4*>(base + 4);
    int4 a1 = *reinterpret_cast<const int4*>(base + 256);
    int4 b1 = *reinterpret_cast<const int4*>(base + 260);

    uint32_t g0 = seg_ge16_regs(a0, b0, sx);
    uint32_t g1 = seg_ge16_regs(a1, b1, sx);
    if (pos == 0) {
        segbuf[w][sg]     = g0;
        segbuf[w][4 + sg] = g1;
    }
    __syncwarp();
    if (lane == 0) {
        uint32_t ge4 = branch_ge4(&segbuf[w][0]);
#pragma unroll
        for (int b = 0; b < 16; b++)
            out[(b * 128 + c) * 16 + br] = ((ge4 >> b) & 1u) ? 1.0f : 0.0f;
    }
}

extern "C" void kernel_launch(void* const* d_in, const int* in_sizes, int n_in,
                              void* d_out, int out_size) {
    const float* x = nullptr;
    const int* idxA = nullptr;
    const int* idxB = nullptr;
    for (int i = 0; i < n_in; i++) {
        if (in_sizes[i] == 262144 && !x) {
            x = (const float*)d_in[i];
        } else if (!idxA) {
            idxA = (const int*)d_in[i];
        } else if (!idxB) {
            idxB = (const int*)d_in[i];
        }
    }
    if (!x) { x = (const float*)d_in[0]; idxA = (const int*)d_in[1]; idxB = (const int*)d_in[2]; }

    float* out = (float*)d_out;   // (16, 128, 16) float32

    k_pack  <<<64, 256>>>(x);
    k_layer1<<<512, 256>>>(idxA);
    k_layer2<<<256, 256>>>(idxB, out);
}

// round 9
// speedup vs baseline: 1.1001x; 1.0014x over previous
#include <cuda_runtime.h>
#include <cuda_bf16.h>
#include <cstdint>

// Constants: B=16, C=128, T=8, BR=16, S=8, SY=64, INPUT_SIZE=16384, C*T*BR=16384
// seg_on = (count>=16 of 64), branch_on = (count>=4 of 8)
// Output = layer2 branch_on at t==0 -> (16,128,16) float32

__device__ __align__(16) uint16_t g_xbits[16384];
__device__ __align__(16) uint16_t g_act1[16384];

__device__ __forceinline__ uint32_t maj3(uint32_t a, uint32_t b, uint32_t c) {
    return (a & b) | (a & c) | (b & c);
}

#define SHFLX(v, m) __shfl_xor_sync(0xffffffffu, (v), (m))

// 8 lanes cooperate on one 64-synapse segment (indices in registers);
// returns on all 8 lanes the 16-bit batch mask of (segment count >= 16).
__device__ __forceinline__ uint32_t seg_ge16_regs(int4 a, int4 b,
                                                  const uint16_t* __restrict__ sx) {
    uint32_t m0 = sx[a.x + 1], m1 = sx[a.y + 1], m2 = sx[a.z + 1], m3 = sx[a.w + 1];
    uint32_t m4 = sx[b.x + 1], m5 = sx[b.y + 1], m6 = sx[b.z + 1], m7 = sx[b.w + 1];

    uint32_t s1 = m0 ^ m1 ^ m2, c1 = maj3(m0, m1, m2);
    uint32_t s2 = m3 ^ m4 ^ m5, c2 = maj3(m3, m4, m5);
    uint32_t s3 = s1 ^ s2 ^ m6, c3 = maj3(s1, s2, m6);
    uint32_t w1 = s3 ^ m7,      c4 = s3 & m7;
    uint32_t s4 = c1 ^ c2 ^ c3, c5 = maj3(c1, c2, c3);
    uint32_t w2 = s4 ^ c4,      c6 = s4 & c4;
    uint32_t w4 = c5 ^ c6,      w8 = c5 & c6;

    uint32_t r0 = SHFLX(w1, 1), r1 = SHFLX(w2, 1), r2 = SHFLX(w4, 1), r3 = SHFLX(w8, 1);
    uint32_t k  = w1 & r0;
    uint32_t t0 = w1 ^ r0;
    uint32_t t1 = w2 ^ r1 ^ k;  k = maj3(w2, r1, k);
    uint32_t t2 = w4 ^ r2 ^ k;  k = maj3(w4, r2, k);
    uint32_t t3 = w8 ^ r3 ^ k;
    uint32_t t4 = maj3(w8, r3, k);

    r0 = SHFLX(t0, 2); r1 = SHFLX(t1, 2); r2 = SHFLX(t2, 2); r3 = SHFLX(t3, 2);
    uint32_t r4 = SHFLX(t4, 2);
    k = t0 & r0;
    uint32_t u0 = t0 ^ r0;
    uint32_t u1 = t1 ^ r1 ^ k;  k = maj3(t1, r1, k);
    uint32_t u2 = t2 ^ r2 ^ k;  k = maj3(t2, r2, k);
    uint32_t u3 = t3 ^ r3 ^ k;  k = maj3(t3, r3, k);
    uint32_t u4 = t4 ^ r4 ^ k;
    uint32_t u5 = maj3(t4, r4, k);

    r0 = SHFLX(u0, 4); r1 = SHFLX(u1, 4); r2 = SHFLX(u2, 4); r3 = SHFLX(u3, 4);
    r4 = SHFLX(u4, 4); uint32_t r5 = SHFLX(u5, 4);
    k = u0 & r0;
    k = maj3(u1, r1, k);
    k = maj3(u2, r2, k);
    k = maj3(u3, r3, k);
    return u4 | r4 | k | u5 | r5;
}

__device__ __forceinline__ uint32_t branch_ge4(const uint32_t* s) {
    uint32_t o01 = s[0] ^ s[1], t01 = s[0] & s[1];
    uint32_t o23 = s[2] ^ s[3], t23 = s[2] & s[3];
    uint32_t o45 = s[4] ^ s[5], t45 = s[4] & s[5];
    uint32_t o67 = s[6] ^ s[7], t67 = s[6] & s[7];
    uint32_t ca  = o01 & o23;
    uint32_t o03 = o01 ^ o23;
    uint32_t t03 = t01 ^ t23 ^ ca;
    uint32_t f03 = maj3(t01, t23, ca);
    uint32_t cb  = o45 & o67;
    uint32_t o47 = o45 ^ o67;
    uint32_t t47 = t45 ^ t67 ^ cb;
    uint32_t f47 = maj3(t45, t67, cb);
    uint32_t c1 = o03 & o47;
    uint32_t c2 = maj3(t03, t47, c1);
    return f03 | f47 | c2;
}

__device__ __forceinline__ void fill_table(uint16_t* sx, const uint16_t* gtab) {
    if (threadIdx.x == 0) sx[0] = 0;
    const uint32_t* src = reinterpret_cast<const uint32_t*>(gtab);
    for (int i = threadIdx.x; i < 8192; i += 256) {
        uint32_t v = src[i];
        sx[1 + 2 * i] = (uint16_t)(v & 0xFFFFu);
        sx[2 + 2 * i] = (uint16_t)(v >> 16);
    }
    __syncthreads();
}

// Pack x (16 x 16384 floats of {0,1}) into per-position 16-bit batch masks.
// 32 blocks x 128 threads; each thread: 16 independent float4 loads (4 positions).
__global__ void __launch_bounds__(128) k_pack(const float4* __restrict__ x4) {
    int g = blockIdx.x * 128 + threadIdx.x;     // 0..4095
    float4 v[16];
#pragma unroll
    for (int b = 0; b < 16; b++) v[b] = x4[b * 4096 + g];
    uint32_t m0 = 0, m1 = 0, m2 = 0, m3 = 0;
#pragma unroll
    for (int b = 0; b < 16; b++) {
        m0 |= (uint32_t)(v[b].x != 0.0f) << b;
        m1 |= (uint32_t)(v[b].y != 0.0f) << b;
        m2 |= (uint32_t)(v[b].z != 0.0f) << b;
        m3 |= (uint32_t)(v[b].w != 0.0f) << b;
    }
    uint2 packed;
    packed.x = m0 | (m1 << 16);
    packed.y = m2 | (m3 << 16);
    reinterpret_cast<uint2*>(g_xbits)[g] = packed;
}

// Layer 1: 512 blocks x 8 warps; warp covers 4 branches = 8 kk slices.
// Two interleaved kk streams (kk, kk+4), each depth-2 prefetched:
// 8 LDG.128 outstanding at start, ~4 in steady state, 2x chain ILP.
__global__ void __launch_bounds__(256, 3) k_layer1(const int* __restrict__ idx) {
    __shared__ uint16_t sx[16386];
    __shared__ uint32_t segbuf[8][32];
    fill_table(sx, g_xbits);

    int w = threadIdx.x >> 5, lane = threadIdx.x & 31;
    int pos = lane & 7, sg = lane >> 3;
    int bb = (blockIdx.x * 8 + w) * 4;
    const int* base = idx + bb * 512 + sg * 64 + pos * 8;

    int4 aA[2], bA[2], aB[2], bB[2];
    aA[0] = *reinterpret_cast<const int4*>(base);
    bA[0] = *reinterpret_cast<const int4*>(base + 4);
    aB[0] = *reinterpret_cast<const int4*>(base + 1024);
    bB[0] = *reinterpret_cast<const int4*>(base + 1028);
    aA[1] = *reinterpret_cast<const int4*>(base + 256);
    bA[1] = *reinterpret_cast<const int4*>(base + 260);
    aB[1] = *reinterpret_cast<const int4*>(base + 1280);
    bB[1] = *reinterpret_cast<const int4*>(base + 1284);

#pragma unroll
    for (int kk = 0; kk < 4; kk++) {
        int4 A0 = aA[kk & 1], B0 = bA[kk & 1];
        int4 A1 = aB[kk & 1], B1 = bB[kk & 1];
        if (kk < 2) {
            aA[kk & 1] = *reinterpret_cast<const int4*>(base + (kk + 2) * 256);
            bA[kk & 1] = *reinterpret_cast<const int4*>(base + (kk + 2) * 256 + 4);
            aB[kk & 1] = *reinterpret_cast<const int4*>(base + (kk + 6) * 256);
            bB[kk & 1] = *reinterpret_cast<const int4*>(base + (kk + 6) * 256 + 4);
        }
        uint32_t g0 = seg_ge16_regs(A0, B0, sx);   // slice kk
        uint32_t g1 = seg_ge16_regs(A1, B1, sx);   // slice kk+4
        if (pos == 0) {
            segbuf[w][kk * 4 + sg]       = g0;
            segbuf[w][(kk + 4) * 4 + sg] = g1;
        }
    }
    __syncwarp();
    if (lane < 4) {
        uint32_t ge4 = branch_ge4(&segbuf[w][lane * 8]);
        g_act1[bb + lane] = (uint16_t)ge4;
    }
}

// Layer 2 (t==0 only): 128 blocks x 8 warps; warp covers 2 branches
// (4 independent seg computations, all 8 int4-pair loads hoisted).
__global__ void __launch_bounds__(256, 4) k_layer2(const int* __restrict__ idx,
                                                   float* __restrict__ out) {
    __shared__ uint16_t sx[16386];
    __shared__ uint32_t segbuf[8][16];
    fill_table(sx, g_act1);

    int w = threadIdx.x >> 5, lane = threadIdx.x & 31;
    int pos = lane & 7, sg = lane >> 3;
    int pr0 = blockIdx.x * 16 + w * 2;            // branch id = c*16 + br
    int pr1 = pr0 + 1;
    const int* base0 = idx + ((pr0 >> 4) * 1024 + (pr0 & 15) * 8 + sg) * 64 + pos * 8;
    const int* base1 = idx + ((pr1 >> 4) * 1024 + (pr1 & 15) * 8 + sg) * 64 + pos * 8;

    int4 a00 = *reinterpret_cast<const int4*>(base0);
    int4 b00 = *reinterpret_cast<const int4*>(base0 + 4);
    int4 a01 = *reinterpret_cast<const int4*>(base0 + 256);
    int4 b01 = *reinterpret_cast<const int4*>(base0 + 260);
    int4 a10 = *reinterpret_cast<const int4*>(base1);
    int4 b10 = *reinterpret_cast<const int4*>(base1 + 4);
    int4 a11 = *reinterpret_cast<const int4*>(base1 + 256);
    int4 b11 = *reinterpret_cast<const int4*>(base1 + 260);

    uint32_t g00 = seg_ge16_regs(a00, b00, sx);
    uint32_t g01 = seg_ge16_regs(a01, b01, sx);
    uint32_t g10 = seg_ge16_regs(a10, b10, sx);
    uint32_t g11 = seg_ge16_regs(a11, b11, sx);
    if (pos == 0) {
        segbuf[w][sg]      = g00;
        segbuf[w][4 + sg]  = g01;
        segbuf[w][8 + sg]  = g10;
        segbuf[w][12 + sg] = g11;
    }
    __syncwarp();
    if (lane < 2) {
        uint32_t ge4 = branch_ge4(&segbuf[w][lane * 8]);
        int pr = pr0 + lane;
        int c = pr >> 4, br = pr & 15;
#pragma unroll
        for (int b = 0; b < 16; b++)
            out[(b * 128 + c) * 16 + br] = ((ge4 >> b) & 1u) ? 1.0f : 0.0f;
    }
}

extern "C" void kernel_launch(void* const* d_in, const int* in_sizes, int n_in,
                              void* d_out, int out_size) {
    const float* x = nullptr;
    const int* idxA = nullptr;
    const int* idxB = nullptr;
    for (int i = 0; i < n_in; i++) {
        if (in_sizes[i] == 262144 && !x) {
            x = (const float*)d_in[i];
        } else if (!idxA) {
            idxA = (const int*)d_in[i];
        } else if (!idxB) {
            idxB = (const int*)d_in[i];
        }
    }
    if (!x) { x = (const float*)d_in[0]; idxA = (const int*)d_in[1]; idxB = (const int*)d_in[2]; }

    float* out = (float*)d_out;   // (16, 128, 16) float32

    k_pack  <<<32, 128>>>(reinterpret_cast<const float4*>(x));
    k_layer1<<<512, 256>>>(idxA);
    k_layer2<<<128, 256>>>(idxB, out);
}